// round 9
// baseline (speedup 1.0000x reference)
#include <cuda_runtime.h>
#include <math.h>

#define TPB 256
#define PPT 2          // consecutive pairs per thread (real-space)
#define MAXA 1024      // atoms staged in shared memory
#define NK_HALF 2456   // half-space of 17^3 grid (indices past center)
#define NB_RECIP 307   // 307*8 warps >= 2456
#define FULLMASK 0xffffffffu

struct AccT {
    double r[32];
    double k[32];
    unsigned int cnt;
    unsigned int pad[31];
};
__device__ AccT g_acc;   // zero-initialized at load; self-resetting per run

__device__ __forceinline__ float blockReduceF(float v) {
    __shared__ float sh[32];
    int lane = threadIdx.x & 31, w = threadIdx.x >> 5;
    #pragma unroll
    for (int o = 16; o; o >>= 1) v += __shfl_down_sync(FULLMASK, v, o);
    if (lane == 0) sh[w] = v;
    __syncthreads();
    if (w == 0) {
        v = (lane < (TPB >> 5)) ? sh[lane] : 0.f;
        #pragma unroll
        for (int o = 16; o; o >>= 1) v += __shfl_down_sync(FULLMASK, v, o);
    }
    return v;
}

// cheap eta: (vol^2/n)^(1/6) / sqrt(2*pi) via MUFU log/exp (rel err ~1e-6)
__device__ __forceinline__ float fast_eta(float vol, int n) {
    return __expf(__logf(vol * vol / (float)n) * 0.16666667f) * 0.39894228040143267f;
}

// AS 7.1.26 polynomial in t = 1/(1+0.3275911 x)
__device__ __forceinline__ float as_poly(float t) {
    return t * fmaf(t, fmaf(t, fmaf(t, fmaf(t, 1.061405429f, -1.453152027f),
           1.421413741f), -0.284496736f), 0.254829592f);
}

// full erfc (slow path)
__device__ __forceinline__ float erfc_as(float x) {
    float t = __fdividef(1.0f, fmaf(0.3275911f, x, 1.0f));
    return as_poly(t) * __expf(-x * x);
}

__global__ void __launch_bounds__(TPB)
k_main(const float* __restrict__ pos, const float* __restrict__ cell,
       const float* __restrict__ q, const float* __restrict__ sigt,
       const int* __restrict__ spec, const int* __restrict__ nsr,
       const int* __restrict__ nkr, float* __restrict__ out,
       int n, int nPairs, unsigned int total_blocks) {
    __shared__ float4 s_pq[MAXA];
    __shared__ float  s_s2[MAXA];    // 2*sigma^2
    int tid = threadIdx.x;
    int b = blockIdx.x;

    int nf = (n < MAXA) ? n : MAXA;
    for (int a = tid; a < nf; a += TPB) {
        s_pq[a] = make_float4(__ldg(pos + 3*a), __ldg(pos + 3*a + 1),
                              __ldg(pos + 3*a + 2), __ldg(q + a));
        float sg = __ldg(sigt + __ldg(spec + a));
        s_s2[a] = 2.0f * sg * sg;
    }
    __syncthreads();

    float c00 = __ldg(cell + 0), c01 = __ldg(cell + 1), c02 = __ldg(cell + 2);
    float c10 = __ldg(cell + 3), c11 = __ldg(cell + 4), c12 = __ldg(cell + 5);
    float c20 = __ldg(cell + 6), c21 = __ldg(cell + 7), c22 = __ldg(cell + 8);
    float det = c00 * (c11 * c22 - c12 * c21)
              - c01 * (c10 * c22 - c12 * c20)
              + c02 * (c10 * c21 - c11 * c20);
    float vol = fabsf(det);
    float eta = fast_eta(vol, n);
    const float SQRT_2LOG = 6.0697085114f;   // sqrt(-2*ln(1e-8))
    float cutr = SQRT_2LOG * eta;
    float cutr2 = cutr * cutr;
    float inve = 0.7071067811865476f / eta;

    if (b < NB_RECIP) {
        // ---------- reciprocal: one WARP per half-space k-vector -------------
        int w = tid >> 5, lane = tid & 31;
        int widx = b * 8 + w;
        if (widx < NK_HALF) {
            int f = 2457 + widx;
            int kx = f % 17 - 8;
            int ky = (f / 17) % 17 - 8;
            int kz = f / 289 - 8;
            int nk = __ldg(nkr);
            if (abs(kx) <= nk && abs(ky) <= nk && abs(kz) <= nk) {
                const float TWO_PI = 6.283185307179586f;
                float id = __fdividef(TWO_PI, det);
                float kax = (kx*(c11*c22-c12*c21) + ky*(c12*c20-c10*c22) + kz*(c10*c21-c11*c20)) * id;
                float kay = (kx*(c02*c21-c01*c22) + ky*(c00*c22-c02*c20) + kz*(c01*c20-c00*c21)) * id;
                float kaz = (kx*(c01*c12-c02*c11) + ky*(c02*c10-c00*c12) + kz*(c00*c11-c01*c10)) * id;
                float k2 = kax*kax + kay*kay + kaz*kaz;
                float cutk = SQRT_2LOG / eta;
                if (k2 > 1e-16f && k2 < cutk * cutk) {
                    float wgt = __fdividef(__expf(-0.5f * eta * eta * k2), k2);
                    float sc = 0.f, ss = 0.f;
                    for (int i2 = lane; i2 < n; i2 += 32) {
                        float4 p = (i2 < MAXA) ? s_pq[i2]
                                 : make_float4(__ldg(pos+3*i2), __ldg(pos+3*i2+1),
                                               __ldg(pos+3*i2+2), __ldg(q+i2));
                        float th = fmaf(kax, p.x, fmaf(kay, p.y, kaz * p.z));
                        th -= TWO_PI * rintf(th * 0.15915494309189535f);
                        float s, c;
                        __sincosf(th, &s, &c);
                        sc = fmaf(p.w, c, sc);
                        ss = fmaf(p.w, s, ss);
                    }
                    #pragma unroll
                    for (int o = 16; o; o >>= 1) {
                        sc += __shfl_down_sync(FULLMASK, sc, o);
                        ss += __shfl_down_sync(FULLMASK, ss, o);
                    }
                    if (lane == 0)
                        atomicAdd(&g_acc.k[widx & 31],
                                  (double)(2.0f * wgt * (sc*sc + ss*ss)));
                }
            }
        }
    } else {
        // ---------- real space: PPT consecutive triangular pairs per thread --
        int t0 = (b - NB_RECIP) * (TPB * PPT) + tid * PPT;
        float local = 0.f;

        int ns = __ldg(nsr);
        bool diag = (c01==0.f && c02==0.f && c10==0.f && c12==0.f && c20==0.f && c21==0.f);
        bool fast = diag && ns >= 1 &&
                    cutr2 <= c00*c00 && cutr2 <= c11*c11 && cutr2 <= c22*c22;

        // (i,j) for first pair
        int tc = (t0 < nPairs) ? t0 : (nPairs - 1);
        int i = (int)(sqrtf(2.0f * (float)tc + 0.25f) - 0.5f);
        if ((i + 1) * (i + 2) / 2 <= tc) ++i;
        if (i * (i + 1) / 2 > tc) --i;
        int j = tc - i * (i + 1) / 2;

        if (fast) {   // warp-uniform
            float iLx = __fdividef(1.0f, c00);
            float iLy = __fdividef(1.0f, c11);
            float iLz = __fdividef(1.0f, c22);
            const float L2E = 1.4426950408889634f;
            float eA = -L2E * inve * inve;

            #pragma unroll
            for (int kk = 0; kk < PPT; ++kk) {
                int t = t0 + kk;
                if (t < nPairs) {
                    float4 Pi = (i < MAXA) ? s_pq[i]
                              : make_float4(__ldg(pos+3*i), __ldg(pos+3*i+1),
                                            __ldg(pos+3*i+2), __ldg(q+i));
                    float4 Pj = (j < MAXA) ? s_pq[j]
                              : make_float4(__ldg(pos+3*j), __ldg(pos+3*j+1),
                                            __ldg(pos+3*j+2), __ldg(q+j));
                    float s2i, s2j;
                    if (i < MAXA) s2i = s_s2[i];
                    else { float sg = __ldg(sigt + __ldg(spec+i)); s2i = 2.f*sg*sg; }
                    if (j < MAXA) s2j = s_s2[j];
                    else { float sg = __ldg(sigt + __ldg(spec+j)); s2j = 2.f*sg*sg; }

                    float dx = Pj.x - Pi.x, dy = Pj.y - Pi.y, dz = Pj.z - Pi.z;
                    float qq = Pi.w * Pj.w * ((j < i) ? 2.0f : 1.0f);
                    float invg  = rsqrtf(s2i + s2j);     // 1/(sqrt2*gamma)
                    float invg2 = invg * invg;
                    float eB = -L2E * invg2;

                    float x0 = fmaf(-c00, rintf(dx * iLx), dx);
                    float y0 = fmaf(-c11, rintf(dy * iLy), dy);
                    float z0 = fmaf(-c22, rintf(dz * iLz), dz);
                    float x1 = x0 - copysignf(c00, x0);
                    float y1 = y0 - copysignf(c11, y0);
                    float z1 = z0 - copysignf(c22, z0);
                    float xs0 = x0*x0, xs1 = x1*x1;
                    float ys0 = y0*y0, ys1 = y1*y1;
                    float zs0 = z0*z0, zs1 = z1*z1;

                    // min image: both erfc chains
                    {
                        float r2 = xs0 + ys0 + zs0;
                        if (r2 > 1e-16f && r2 < cutr2) {
                            float rinv = rsqrtf(r2);
                            float r = r2 * rinv;
                            float vA = as_poly(__frcp_rn(fmaf(0.3275911f, r * inve, 1.0f)))
                                       * exp2f(r2 * eA);
                            float vB = as_poly(__frcp_rn(fmaf(0.3275911f, r * invg, 1.0f)))
                                       * exp2f(r2 * eB);
                            local = fmaf(qq, (vA - vB) * rinv, local);
                        }
                    }
                    // secondary images: lane-local mask pop loop, eta-chain only
                    unsigned int mask = 0u;
                    #pragma unroll
                    for (int c = 1; c < 8; ++c) {
                        float r2 = ((c & 1) ? xs1 : xs0) + ((c & 2) ? ys1 : ys0)
                                 + ((c & 4) ? zs1 : zs0);
                        mask |= (r2 < cutr2 ? 1u : 0u) << c;
                    }
                    while (mask) {
                        int c = __ffs(mask) - 1;
                        mask &= mask - 1;
                        float r2 = ((c & 1) ? xs1 : xs0) + ((c & 2) ? ys1 : ys0)
                                 + ((c & 4) ? zs1 : zs0);
                        float rinv = rsqrtf(r2);
                        float r = r2 * rinv;
                        float v = as_poly(__frcp_rn(fmaf(0.3275911f, r * inve, 1.0f)))
                                  * exp2f(r2 * eA);
                        if (r2 * invg2 < 16.5f)   // erfc(x) non-negligible (never for r>=L/2 here)
                            v -= as_poly(__frcp_rn(fmaf(0.3275911f, r * invg, 1.0f)))
                                 * exp2f(r2 * eB);
                        local = fmaf(qq, v * rinv, local);
                    }
                }
                // advance to next consecutive pair
                ++j;
                if (j > i) { ++i; j = 0; }
            }
        } else {
            #pragma unroll
            for (int kk = 0; kk < PPT; ++kk) {
                int t = t0 + kk;
                if (t < nPairs) {
                    float dx = __ldg(pos+3*j)   - __ldg(pos+3*i);
                    float dy = __ldg(pos+3*j+1) - __ldg(pos+3*i+1);
                    float dz = __ldg(pos+3*j+2) - __ldg(pos+3*i+2);
                    float qq = __ldg(q+i) * __ldg(q+j) * ((j < i) ? 2.0f : 1.0f);
                    float si = __ldg(sigt + __ldg(spec+i));
                    float sj = __ldg(sigt + __ldg(spec+j));
                    float invg = rsqrtf(2.f * (si*si + sj*sj));

                    for (int sx = -ns; sx <= ns; ++sx)
                        for (int sy = -ns; sy <= ns; ++sy) {
                            float bx = dx + sx*c00 + sy*c10;
                            float by = dy + sx*c01 + sy*c11;
                            float bz = dz + sx*c02 + sy*c12;
                            for (int sz = -ns; sz <= ns; ++sz) {
                                float ax = bx + sz*c20, ay = by + sz*c21, az = bz + sz*c22;
                                float r2 = ax*ax + ay*ay + az*az;
                                if (r2 > 1e-16f && r2 < cutr2) {
                                    float rinv = rsqrtf(r2);
                                    float r = r2 * rinv;
                                    local += qq * (erfc_as(r*inve) - erfc_as(r*invg)) * rinv;
                                }
                            }
                        }
                }
                ++j;
                if (j > i) { ++i; j = 0; }
            }
        }
        float tot = blockReduceF(local);
        if (tid == 0) atomicAdd(&g_acc.r[b & 31], (double)tot);
    }

    // ---------------- last block: self term + combine + RESET ---------------
    __shared__ bool isLast;
    __syncthreads();
    if (tid == 0) {
        __threadfence();
        unsigned int prev = atomicAdd(&g_acc.cnt, 1u);
        isLast = (prev == total_blocks - 1);
    }
    __syncthreads();
    if (!isLast) return;

    __shared__ double shd[64];
    if (tid < 64)
        shd[tid] = (tid < 32) ? __ldcg(&g_acc.r[tid]) : __ldcg(&g_acc.k[tid - 32]);
    __syncthreads();

    if (tid < 32) { g_acc.r[tid] = 0.0; g_acc.k[tid] = 0.0; }
    if (tid == 0) g_acc.cnt = 0u;

    float a = -0.7978845608028654f / eta;
    float selfLocal = 0.f;
    for (int i2 = tid; i2 < n; i2 += TPB) {
        float qv, s2;
        if (i2 < MAXA) { qv = s_pq[i2].w; s2 = s_s2[i2]; }
        else {
            qv = __ldg(q + i2);
            float sg = __ldg(sigt + __ldg(spec + i2));
            s2 = 2.f * sg * sg;
        }
        float sg2 = sqrtf(0.5f * s2);   // sigma
        selfLocal += qv * qv * (a + 0.5641895835477563f / sg2);
    }
    float selfSum = blockReduceF(selfLocal);
    if (tid == 0) {
        double sr = 0.0, sk = 0.0;
        #pragma unroll
        for (int tt = 0; tt < 32; ++tt) { sr += shd[tt]; sk += shd[32 + tt]; }
        const double COEF = 14.399645478425668;
        double E = 0.5 * COEF * (sr + (4.0 * M_PI / (double)vol) * sk + (double)selfSum);
        out[0] = (float)E;
    }
}

extern "C" void kernel_launch(void* const* d_in, const int* in_sizes, int n_in,
                              void* d_out, int out_size) {
    const float* pos  = (const float*)d_in[0];
    const float* cell = (const float*)d_in[1];
    const float* q    = (const float*)d_in[2];
    const float* sigt = (const float*)d_in[3];
    const int*   spec = (const int*)d_in[4];
    const int*   nsr  = (const int*)d_in[5];
    const int*   nkr  = (const int*)d_in[6];
    int n = in_sizes[0] / 3;

    int nPairs = n * (n + 1) / 2;
    int nbReal = (nPairs + TPB * PPT - 1) / (TPB * PPT);
    unsigned int total = NB_RECIP + nbReal;
    k_main<<<total, TPB>>>(pos, cell, q, sigt, spec, nsr, nkr,
                           (float*)d_out, n, nPairs, total);
}

// round 10
// speedup vs baseline: 1.1212x; 1.1212x over previous
#include <cuda_runtime.h>
#include <math.h>

#define TPB 256
#define TS 32          // atom tile size
#define NK_HALF 2456   // half-space of 17^3 grid (indices past center)
#define NB_RECIP 307   // 307*8 warps >= 2456
#define FULLMASK 0xffffffffu

struct AccT {
    double r[32];
    double k[32];
    unsigned int cnt;
    unsigned int pad[31];
};
__device__ AccT g_acc;   // zero-initialized at load; self-resetting per run

__device__ __forceinline__ float blockReduceF(float v) {
    __shared__ float sh[32];
    int lane = threadIdx.x & 31, w = threadIdx.x >> 5;
    #pragma unroll
    for (int o = 16; o; o >>= 1) v += __shfl_down_sync(FULLMASK, v, o);
    if (lane == 0) sh[w] = v;
    __syncthreads();
    if (w == 0) {
        v = (lane < (TPB >> 5)) ? sh[lane] : 0.f;
        #pragma unroll
        for (int o = 16; o; o >>= 1) v += __shfl_down_sync(FULLMASK, v, o);
    }
    return v;
}

// cheap eta: (vol^2/n)^(1/6) / sqrt(2*pi) via MUFU log/exp (rel err ~1e-6)
__device__ __forceinline__ float fast_eta(float vol, int n) {
    return __expf(__logf(vol * vol / (float)n) * 0.16666667f) * 0.39894228040143267f;
}

// AS 7.1.26 polynomial in t = 1/(1+0.3275911 x)
__device__ __forceinline__ float as_poly(float t) {
    return t * fmaf(t, fmaf(t, fmaf(t, fmaf(t, 1.061405429f, -1.453152027f),
           1.421413741f), -0.284496736f), 0.254829592f);
}

// full erfc (slow path)
__device__ __forceinline__ float erfc_as(float x) {
    float t = __fdividef(1.0f, fmaf(0.3275911f, x, 1.0f));
    return as_poly(t) * __expf(-x * x);
}

__global__ void __launch_bounds__(TPB)
k_main(const float* __restrict__ pos, const float* __restrict__ cell,
       const float* __restrict__ q, const float* __restrict__ sigt,
       const int* __restrict__ spec, const int* __restrict__ nsr,
       const int* __restrict__ nkr, float* __restrict__ out,
       int n, unsigned int total_blocks) {
    __shared__ float4 sj_pq[TS];
    __shared__ float  sj_s2[TS];
    int tid = threadIdx.x;
    int b = blockIdx.x;

    float c00 = __ldg(cell + 0), c01 = __ldg(cell + 1), c02 = __ldg(cell + 2);
    float c10 = __ldg(cell + 3), c11 = __ldg(cell + 4), c12 = __ldg(cell + 5);
    float c20 = __ldg(cell + 6), c21 = __ldg(cell + 7), c22 = __ldg(cell + 8);
    float det = c00 * (c11 * c22 - c12 * c21)
              - c01 * (c10 * c22 - c12 * c20)
              + c02 * (c10 * c21 - c11 * c20);
    float vol = fabsf(det);
    float eta = fast_eta(vol, n);
    const float SQRT_2LOG = 6.0697085114f;   // sqrt(-2*ln(1e-8))
    float cutr = SQRT_2LOG * eta;
    float cutr2 = cutr * cutr;
    float inve = 0.7071067811865476f / eta;

    if (b < NB_RECIP) {
        // ---------- reciprocal: one WARP per half-space k-vector -------------
        int w = tid >> 5, lane = tid & 31;
        int widx = b * 8 + w;
        if (widx < NK_HALF) {
            int f = 2457 + widx;
            int kx = f % 17 - 8;
            int ky = (f / 17) % 17 - 8;
            int kz = f / 289 - 8;
            int nk = __ldg(nkr);
            if (abs(kx) <= nk && abs(ky) <= nk && abs(kz) <= nk) {
                const float TWO_PI = 6.283185307179586f;
                float id = __fdividef(TWO_PI, det);
                float kax = (kx*(c11*c22-c12*c21) + ky*(c12*c20-c10*c22) + kz*(c10*c21-c11*c20)) * id;
                float kay = (kx*(c02*c21-c01*c22) + ky*(c00*c22-c02*c20) + kz*(c01*c20-c00*c21)) * id;
                float kaz = (kx*(c01*c12-c02*c11) + ky*(c02*c10-c00*c12) + kz*(c00*c11-c01*c10)) * id;
                float k2 = kax*kax + kay*kay + kaz*kaz;
                float cutk = SQRT_2LOG / eta;
                if (k2 > 1e-16f && k2 < cutk * cutk) {
                    float wgt = __fdividef(__expf(-0.5f * eta * eta * k2), k2);
                    float sc = 0.f, ss = 0.f;
                    for (int i2 = lane; i2 < n; i2 += 32) {
                        float th = fmaf(kax, __ldg(pos+3*i2),
                                   fmaf(kay, __ldg(pos+3*i2+1), kaz * __ldg(pos+3*i2+2)));
                        th -= TWO_PI * rintf(th * 0.15915494309189535f);
                        float s, c;
                        __sincosf(th, &s, &c);
                        float qv = __ldg(q + i2);
                        sc = fmaf(qv, c, sc);
                        ss = fmaf(qv, s, ss);
                    }
                    #pragma unroll
                    for (int o = 16; o; o >>= 1) {
                        sc += __shfl_down_sync(FULLMASK, sc, o);
                        ss += __shfl_down_sync(FULLMASK, ss, o);
                    }
                    if (lane == 0)
                        atomicAdd(&g_acc.k[widx & 31],
                                  (double)(2.0f * wgt * (sc*sc + ss*ss)));
                }
            }
        }
    } else {
        // ---------- real space: one block per ordered 32x32 tile pair --------
        int bt = b - NB_RECIP;
        int ti = (int)(sqrtf(2.0f * (float)bt + 0.25f) - 0.5f);
        if ((ti + 1) * (ti + 2) / 2 <= bt) ++ti;
        if (ti * (ti + 1) / 2 > bt) --ti;
        int tj = bt - ti * (ti + 1) / 2;     // tj <= ti

        // stage j-tile (32 atoms) into shared memory
        if (tid < TS) {
            int a = tj * TS + tid;
            if (a < n) {
                sj_pq[tid] = make_float4(__ldg(pos+3*a), __ldg(pos+3*a+1),
                                         __ldg(pos+3*a+2), __ldg(q+a));
                float sg = __ldg(sigt + __ldg(spec + a));
                sj_s2[tid] = 2.0f * sg * sg;
            } else {
                sj_pq[tid] = make_float4(0.f, 0.f, 0.f, 0.f);
                sj_s2[tid] = 1.0f;
            }
        }
        __syncthreads();

        // own i-atom (register resident)
        int li = tid & 31;
        int i = ti * TS + li;
        bool iok = (i < n);
        int ic = iok ? i : 0;
        float pix = __ldg(pos + 3*ic), piy = __ldg(pos + 3*ic + 1), piz = __ldg(pos + 3*ic + 2);
        float qi  = __ldg(q + ic);
        float sgi = __ldg(sigt + __ldg(spec + ic));
        float s2i = 2.0f * sgi * sgi;

        int jj0 = (tid >> 5) * 4;   // 8 warps x 4 j's = full 32-atom j-tile
        float local = 0.f;

        int ns = __ldg(nsr);
        bool diag = (c01==0.f && c02==0.f && c10==0.f && c12==0.f && c20==0.f && c21==0.f);
        bool fast = diag && ns >= 1 &&
                    cutr2 <= c00*c00 && cutr2 <= c11*c11 && cutr2 <= c22*c22;

        if (fast) {   // warp-uniform
            float iLx = __fdividef(1.0f, c00);
            float iLy = __fdividef(1.0f, c11);
            float iLz = __fdividef(1.0f, c22);
            const float L2E = 1.4426950408889634f;
            float eA = -L2E * inve * inve;

            #pragma unroll
            for (int u = 0; u < 4; ++u) {
                int jl = jj0 + u;
                int j = tj * TS + jl;
                float4 Pj = sj_pq[jl];        // uniform within warp
                float s2j = sj_s2[jl];

                float wgt = 0.f;
                if (iok && j < n)
                    wgt = (ti != tj) ? 2.0f : ((j < i) ? 2.0f : ((j == i) ? 1.0f : 0.0f));
                float qq = wgt * qi * Pj.w;

                float dx = Pj.x - pix, dy = Pj.y - piy, dz = Pj.z - piz;
                float invg  = rsqrtf(s2i + s2j);   // 1/(sqrt2*gamma)
                float invg2 = invg * invg;
                float eB = -L2E * invg2;

                float x0 = fmaf(-c00, rintf(dx * iLx), dx);
                float y0 = fmaf(-c11, rintf(dy * iLy), dy);
                float z0 = fmaf(-c22, rintf(dz * iLz), dz);
                float x1 = x0 - copysignf(c00, x0);
                float y1 = y0 - copysignf(c11, y0);
                float z1 = z0 - copysignf(c22, z0);
                float xs0 = x0*x0, xs1 = x1*x1;
                float ys0 = y0*y0, ys1 = y1*y1;
                float zs0 = z0*z0, zs1 = z1*z1;

                // min image: both erfc chains
                {
                    float r2 = xs0 + ys0 + zs0;
                    if (r2 > 1e-16f && r2 < cutr2) {
                        float rinv = rsqrtf(r2);
                        float r = r2 * rinv;
                        float vA = as_poly(__frcp_rn(fmaf(0.3275911f, r * inve, 1.0f)))
                                   * exp2f(r2 * eA);
                        float vB = as_poly(__frcp_rn(fmaf(0.3275911f, r * invg, 1.0f)))
                                   * exp2f(r2 * eB);
                        local = fmaf(qq, (vA - vB) * rinv, local);
                    }
                }
                // secondary images: lane-local mask pop, eta-chain (+ guarded gamma)
                unsigned int mask = 0u;
                #pragma unroll
                for (int c = 1; c < 8; ++c) {
                    float r2 = ((c & 1) ? xs1 : xs0) + ((c & 2) ? ys1 : ys0)
                             + ((c & 4) ? zs1 : zs0);
                    mask |= (r2 < cutr2 ? 1u : 0u) << c;
                }
                while (mask) {
                    int c = __ffs(mask) - 1;
                    mask &= mask - 1;
                    float r2 = ((c & 1) ? xs1 : xs0) + ((c & 2) ? ys1 : ys0)
                             + ((c & 4) ? zs1 : zs0);
                    float rinv = rsqrtf(r2);
                    float r = r2 * rinv;
                    float v = as_poly(__frcp_rn(fmaf(0.3275911f, r * inve, 1.0f)))
                              * exp2f(r2 * eA);
                    if (r2 * invg2 < 16.5f)   // gamma-erfc non-negligible (rare: r>=L/2)
                        v -= as_poly(__frcp_rn(fmaf(0.3275911f, r * invg, 1.0f)))
                             * exp2f(r2 * eB);
                    local = fmaf(qq, v * rinv, local);
                }
            }
        } else {
            #pragma unroll 1
            for (int u = 0; u < 4; ++u) {
                int jl = jj0 + u;
                int j = tj * TS + jl;
                float4 Pj = sj_pq[jl];
                float s2j = sj_s2[jl];
                float wgt = 0.f;
                if (iok && j < n)
                    wgt = (ti != tj) ? 2.0f : ((j < i) ? 2.0f : ((j == i) ? 1.0f : 0.0f));
                float qq = wgt * qi * Pj.w;
                float dx = Pj.x - pix, dy = Pj.y - piy, dz = Pj.z - piz;
                float invg = rsqrtf(s2i + s2j);

                for (int sx = -ns; sx <= ns; ++sx)
                    for (int sy = -ns; sy <= ns; ++sy) {
                        float bx = dx + sx*c00 + sy*c10;
                        float by = dy + sx*c01 + sy*c11;
                        float bz = dz + sx*c02 + sy*c12;
                        for (int sz = -ns; sz <= ns; ++sz) {
                            float ax = bx + sz*c20, ay = by + sz*c21, az = bz + sz*c22;
                            float r2 = ax*ax + ay*ay + az*az;
                            if (r2 > 1e-16f && r2 < cutr2) {
                                float rinv = rsqrtf(r2);
                                float r = r2 * rinv;
                                local += qq * (erfc_as(r*inve) - erfc_as(r*invg)) * rinv;
                            }
                        }
                    }
            }
        }
        float tot = blockReduceF(local);
        if (tid == 0) atomicAdd(&g_acc.r[b & 31], (double)tot);
    }

    // ---------------- last block: self term + combine + RESET ---------------
    __shared__ bool isLast;
    __syncthreads();
    if (tid == 0) {
        __threadfence();
        unsigned int prev = atomicAdd(&g_acc.cnt, 1u);
        isLast = (prev == total_blocks - 1);
    }
    __syncthreads();
    if (!isLast) return;

    __shared__ double shd[64];
    if (tid < 64)
        shd[tid] = (tid < 32) ? __ldcg(&g_acc.r[tid]) : __ldcg(&g_acc.k[tid - 32]);
    __syncthreads();

    if (tid < 32) { g_acc.r[tid] = 0.0; g_acc.k[tid] = 0.0; }
    if (tid == 0) g_acc.cnt = 0u;

    float a = -0.7978845608028654f / eta;
    float selfLocal = 0.f;
    for (int i2 = tid; i2 < n; i2 += TPB) {
        float qv = __ldg(q + i2);
        float sg = __ldg(sigt + __ldg(spec + i2));
        selfLocal += qv * qv * (a + 0.5641895835477563f / sg);
    }
    float selfSum = blockReduceF(selfLocal);
    if (tid == 0) {
        double sr = 0.0, sk = 0.0;
        #pragma unroll
        for (int tt = 0; tt < 32; ++tt) { sr += shd[tt]; sk += shd[32 + tt]; }
        const double COEF = 14.399645478425668;
        double E = 0.5 * COEF * (sr + (4.0 * M_PI / (double)vol) * sk + (double)selfSum);
        out[0] = (float)E;
    }
}

extern "C" void kernel_launch(void* const* d_in, const int* in_sizes, int n_in,
                              void* d_out, int out_size) {
    const float* pos  = (const float*)d_in[0];
    const float* cell = (const float*)d_in[1];
    const float* q    = (const float*)d_in[2];
    const float* sigt = (const float*)d_in[3];
    const int*   spec = (const int*)d_in[4];
    const int*   nsr  = (const int*)d_in[5];
    const int*   nkr  = (const int*)d_in[6];
    int n = in_sizes[0] / 3;

    int nt = (n + TS - 1) / TS;
    int nTilePairs = nt * (nt + 1) / 2;
    unsigned int total = NB_RECIP + nTilePairs;
    k_main<<<total, TPB>>>(pos, cell, q, sigt, spec, nsr, nkr,
                           (float*)d_out, n, total);
}